// round 15
// baseline (speedup 1.0000x reference)
#include <cuda_runtime.h>
#include <cstdint>

// YOLO post-process: (16, 25200, 85) fp32 -> (16, 25200, 6) fp32
//
// R14 (final form): best-measured schedule (R7) + direct-store epilogue.
//   - 128-row (43520 B) tiles, depth-2 cp.async.bulk pipeline, 2 blocks/SM
//   - static contiguous quad-aligned chunks (0.3% skew, zero coordination)
//   - thread-per-row compute from smem (stride-85 scalar LDS = conflict-free)
//   - 4-way unrolled argmax, ordered merge (first-index tie-break)
//   - direct float2 stores (contiguous 24B/row; warp region fully covered)
// Measured invariant: 5.6-5.75 TB/s across 7 schedule variants => HBM-pattern
// ceiling; dur == traffic/BW. This is the bandwidth-duration fixed point.

#define N_ROWS        403200          // 16 * 25200
#define N_CH          85
#define N_OUT         6
#define CONF_TH       0.25f
#define TILE_ROWS     128
#define BLOCK_THREADS 128
#define TILE_FLOATS   (TILE_ROWS * N_CH)     // 10880
#define TILE_BYTES    (TILE_FLOATS * 4)      // 43520
#define GRID_BLOCKS   296                    // 2 per SM * 148

// Chunking in quad-rows (4 rows = 1360 B -> bulk-copy sources 16B-aligned):
//   total quads = 100800 = 296*340 + 160 -> first 160 blocks get 341 quads.
#define QUADS_BASE    340
#define QUADS_EXTRA   160

// dynamic smem: [0,16) mbar[2], [32, +2*TILE_BYTES) in bufs
#define SM_IN    32
#define SM_TOTAL (SM_IN + 2 * TILE_BYTES)    // 87072

__device__ __forceinline__ unsigned smem_u32(const void* p) {
    unsigned a;
    asm("{ .reg .u64 t; cvta.to.shared.u64 t, %1; cvt.u32.u64 %0, t; }"
        : "=r"(a) : "l"(p));
    return a;
}

__device__ __forceinline__ void mbar_init(unsigned addr, unsigned count) {
    asm volatile("mbarrier.init.shared.b64 [%0], %1;" :: "r"(addr), "r"(count) : "memory");
}

__device__ __forceinline__ void bulk_load(unsigned dst_smem, const void* gsrc,
                                          unsigned bytes, unsigned mbar) {
    asm volatile("mbarrier.arrive.expect_tx.shared.b64 _, [%0], %1;"
                 :: "r"(mbar), "r"(bytes) : "memory");
    asm volatile("cp.async.bulk.shared::cta.global.mbarrier::complete_tx::bytes "
                 "[%0], [%1], %2, [%3];"
                 :: "r"(dst_smem), "l"(gsrc), "r"(bytes), "r"(mbar) : "memory");
}

__device__ __forceinline__ void mbar_wait(unsigned addr, unsigned parity) {
    asm volatile(
        "{\n\t"
        ".reg .pred P;\n\t"
        "W%=:\n\t"
        "mbarrier.try_wait.parity.acquire.cta.shared::cta.b64 P, [%0], %1, 0x989680;\n\t"
        "@P bra D%=;\n\t"
        "bra W%=;\n\t"
        "D%=:\n\t"
        "}"
        :: "r"(addr), "r"(parity) : "memory");
}

__global__ __launch_bounds__(BLOCK_THREADS, 2)
void yolo_post_kernel(const float* __restrict__ in, float2* __restrict__ out2)
{
    extern __shared__ char sb[];
    const unsigned base = smem_u32(sb);
    float* const in_base = reinterpret_cast<float*>(sb + SM_IN);

    const int tid = threadIdx.x;
    const int b   = blockIdx.x;

    // Contiguous chunk (quad-row granularity).
    const int q_start = QUADS_BASE * b + (b < QUADS_EXTRA ? b : QUADS_EXTRA);
    const int row0    = 4 * q_start;
    const int n_rows  = 4 * (QUADS_BASE + (b < QUADS_EXTRA ? 1 : 0));   // 1364 or 1360
    const int n_tiles = (n_rows + TILE_ROWS - 1) / TILE_ROWS;           // 11

    if (tid == 0) {
        mbar_init(base + 0, 1);
        mbar_init(base + 8, 1);
        // Prologue: issue DMA for tile 0 into slot 0.
        int tr0 = (n_rows < TILE_ROWS) ? n_rows : TILE_ROWS;
        bulk_load(base + SM_IN, in + (size_t)row0 * N_CH,
                  (unsigned)(tr0 * N_CH * 4), base + 0);
    }
    __syncthreads();

    for (int it = 0; it < n_tiles; ++it) {
        const int slot   = it & 1;
        const int slot_w = (it + 1) & 1;

        // Issue DMA for the next tile into the buffer freed last iteration
        // (its consumers finished before the previous loop-bottom sync).
        if (tid == 0 && it + 1 < n_tiles) {
            const int r_off = (it + 1) * TILE_ROWS;
            int tr = n_rows - r_off;
            if (tr > TILE_ROWS) tr = TILE_ROWS;
            bulk_load(base + SM_IN + slot_w * TILE_BYTES,
                      in + (size_t)(row0 + r_off) * N_CH,
                      (unsigned)(tr * N_CH * 4), base + slot_w * 8);
        }

        // Wait for the current tile's DMA.
        mbar_wait(base + slot * 8, (unsigned)((it >> 1) & 1));

        const int r_off = it * TILE_ROWS;
        int tile_rows = n_rows - r_off;
        if (tile_rows > TILE_ROWS) tile_rows = TILE_ROWS;

        // ---- compute: thread-per-row (stride-85 LDS = conflict-free) ----
        if (tid < tile_rows) {
            const float* row = in_base + slot * TILE_FLOATS + tid * N_CH;

            const float x    = row[0];
            const float y    = row[1];
            const float w    = row[2];
            const float h    = row[3];
            const float conf = row[4];

            float b0 = row[5 +  0], b1 = row[5 + 20], b2 = row[5 + 40], b3 = row[5 + 60];
            int   i0 = 0,           i1 = 20,          i2 = 40,          i3 = 60;

            #pragma unroll
            for (int c = 1; c < 20; c++) {
                float v0 = row[5 +  0 + c];
                float v1 = row[5 + 20 + c];
                float v2 = row[5 + 40 + c];
                float v3 = row[5 + 60 + c];
                if (v0 > b0) { b0 = v0; i0 =  0 + c; }
                if (v1 > b1) { b1 = v1; i1 = 20 + c; }
                if (v2 > b2) { b2 = v2; i2 = 40 + c; }
                if (v3 > b3) { b3 = v3; i3 = 60 + c; }
            }
            // Ordered merge: ties keep the earlier quarter -> first-index semantics.
            if (b1 > b0) { b0 = b1; i0 = i1; }
            if (b2 > b0) { b0 = b2; i0 = i2; }
            if (b3 > b0) { b0 = b3; i0 = i3; }

            const float score = conf * b0;
            const bool  pass  = score > CONF_TH;
            const float hw = 0.5f * w;
            const float hh = 0.5f * h;

            float o0 = 0.f, o1 = 0.f, o2 = 0.f, o3 = 0.f, o4 = 0.f, o5 = 0.f;
            if (pass) {
                o0 = x - hw;
                o1 = y - hh;
                o2 = x + hw;
                o3 = y + hh;
                o4 = score;
                o5 = (float)i0;
            }

            // Direct store: 3x STG.64, 8B-aligned; warp rows contiguous ->
            // fully covered 768B region, L2 merges to full sectors.
            float2* dst = out2 + (size_t)(row0 + r_off + tid) * 3;
            dst[0] = make_float2(o0, o1);
            dst[1] = make_float2(o2, o3);
            dst[2] = make_float2(o4, o5);
        }

        // Slot-reuse fence: every thread's LDS reads of this slot are done
        // before tid 0 re-issues a DMA into it (top of iteration it+1).
        __syncthreads();
    }
}

extern "C" void kernel_launch(void* const* d_in, const int* in_sizes, int n_in,
                              void* d_out, int out_size)
{
    const float* in  = (const float*)d_in[0];
    float2*      out = (float2*)d_out;
    cudaFuncSetAttribute(yolo_post_kernel,
                         cudaFuncAttributeMaxDynamicSharedMemorySize, SM_TOTAL);
    yolo_post_kernel<<<GRID_BLOCKS, BLOCK_THREADS, SM_TOTAL>>>(in, out);
}

// round 17
// speedup vs baseline: 1.0153x; 1.0153x over previous
#include <cuda_runtime.h>
#include <cstdint>

// YOLO post-process: (16, 25200, 85) fp32 -> (16, 25200, 6) fp32
//
// R16 (final): best-measured schedule (R7, 27.10us) + L2 evict-first policy
// on both streams, store fixed to the policy-operand form
// (st.global.L2::cache_hint.v4.f32 ..., policy).
//   - 128-row (43520 B) tiles, depth-2 cp.async.bulk pipeline, 2 blocks/SM
//   - static contiguous quad-aligned chunks (0.3% skew, zero coordination)
//   - thread-per-row compute from smem (stride-85 scalar LDS = conflict-free)
//   - 4-way unrolled argmax, ordered merge (first-index tie-break)
//   - staged float4 output epilogue (512B/warp fully-merged store instrs)
// Measured invariant over 8 schedule variants: 5.6-5.75 TB/s; dur==traffic/BW.

#define N_ROWS        403200          // 16 * 25200
#define N_CH          85
#define N_OUT         6
#define CONF_TH       0.25f
#define TILE_ROWS     128
#define BLOCK_THREADS 128
#define TILE_FLOATS   (TILE_ROWS * N_CH)     // 10880
#define TILE_BYTES    (TILE_FLOATS * 4)      // 43520
#define OUT_FLOATS    (TILE_ROWS * N_OUT)    // 768
#define GRID_BLOCKS   296                    // 2 per SM * 148

// Chunking in quad-rows (4 rows = 1360 B -> bulk-copy sources 16B-aligned):
//   total quads = 100800 = 296*340 + 160 -> first 160 blocks get 341 quads.
#define QUADS_BASE    340
#define QUADS_EXTRA   160

// dynamic smem: [0,16) mbar[2], [32,+2T) in bufs, then 2 out bufs (3072 B)
#define SM_IN    32
#define SM_OUT   (SM_IN + 2 * TILE_BYTES)            // 87072
#define SM_TOTAL (SM_OUT + 2 * OUT_FLOATS * 4)       // 93216

__device__ __forceinline__ unsigned smem_u32(const void* p) {
    unsigned a;
    asm("{ .reg .u64 t; cvta.to.shared.u64 t, %1; cvt.u32.u64 %0, t; }"
        : "=r"(a) : "l"(p));
    return a;
}

__device__ __forceinline__ void mbar_init(unsigned addr, unsigned count) {
    asm volatile("mbarrier.init.shared.b64 [%0], %1;" :: "r"(addr), "r"(count) : "memory");
}

__device__ __forceinline__ uint64_t mk_evict_first_policy() {
    uint64_t pol;
    asm("createpolicy.fractional.L2::evict_first.b64 %0, 1.0;" : "=l"(pol));
    return pol;
}

__device__ __forceinline__ void bulk_load_ef(unsigned dst_smem, const void* gsrc,
                                             unsigned bytes, unsigned mbar,
                                             uint64_t pol) {
    asm volatile("mbarrier.arrive.expect_tx.shared.b64 _, [%0], %1;"
                 :: "r"(mbar), "r"(bytes) : "memory");
    asm volatile("cp.async.bulk.shared::cta.global.mbarrier::complete_tx::bytes"
                 ".L2::cache_hint [%0], [%1], %2, [%3], %4;"
                 :: "r"(dst_smem), "l"(gsrc), "r"(bytes), "r"(mbar), "l"(pol)
                 : "memory");
}

__device__ __forceinline__ void mbar_wait(unsigned addr, unsigned parity) {
    asm volatile(
        "{\n\t"
        ".reg .pred P;\n\t"
        "W%=:\n\t"
        "mbarrier.try_wait.parity.acquire.cta.shared::cta.b64 P, [%0], %1, 0x989680;\n\t"
        "@P bra D%=;\n\t"
        "bra W%=;\n\t"
        "D%=:\n\t"
        "}"
        :: "r"(addr), "r"(parity) : "memory");
}

// Vector store with L2 eviction policy (policy-operand form).
__device__ __forceinline__ void stg128_ef(float4* ptr, float4 v, uint64_t pol) {
    asm volatile("st.global.L2::cache_hint.v4.f32 [%0], {%1, %2, %3, %4}, %5;"
                 :: "l"(ptr), "f"(v.x), "f"(v.y), "f"(v.z), "f"(v.w), "l"(pol)
                 : "memory");
}

__global__ __launch_bounds__(BLOCK_THREADS, 2)
void yolo_post_kernel(const float* __restrict__ in, float4* __restrict__ out4)
{
    extern __shared__ char sb[];
    const unsigned base = smem_u32(sb);
    float* const in_base  = reinterpret_cast<float*>(sb + SM_IN);
    float* const out_base = reinterpret_cast<float*>(sb + SM_OUT);

    const int tid = threadIdx.x;
    const int b   = blockIdx.x;
    const uint64_t pol = mk_evict_first_policy();

    // Contiguous chunk (quad-row granularity).
    const int q_start = QUADS_BASE * b + (b < QUADS_EXTRA ? b : QUADS_EXTRA);
    const int row0    = 4 * q_start;
    const int n_rows  = 4 * (QUADS_BASE + (b < QUADS_EXTRA ? 1 : 0));   // 1364 or 1360
    const int n_tiles = (n_rows + TILE_ROWS - 1) / TILE_ROWS;           // 11

    if (tid == 0) {
        mbar_init(base + 0, 1);
        mbar_init(base + 8, 1);
        // Prologue: issue DMA for tile 0 into slot 0.
        int tr0 = (n_rows < TILE_ROWS) ? n_rows : TILE_ROWS;
        bulk_load_ef(base + SM_IN, in + (size_t)row0 * N_CH,
                     (unsigned)(tr0 * N_CH * 4), base + 0, pol);
    }
    __syncthreads();

    for (int it = 0; it < n_tiles; ++it) {
        const int slot   = it & 1;
        const int slot_w = (it + 1) & 1;

        // Issue DMA for the next tile into the buffer freed last iteration.
        if (tid == 0 && it + 1 < n_tiles) {
            const int r_off = (it + 1) * TILE_ROWS;
            int tr = n_rows - r_off;
            if (tr > TILE_ROWS) tr = TILE_ROWS;
            bulk_load_ef(base + SM_IN + slot_w * TILE_BYTES,
                         in + (size_t)(row0 + r_off) * N_CH,
                         (unsigned)(tr * N_CH * 4), base + slot_w * 8, pol);
        }

        // Wait for current tile.
        mbar_wait(base + slot * 8, (unsigned)((it >> 1) & 1));

        const int r_off = it * TILE_ROWS;
        int tile_rows = n_rows - r_off;
        if (tile_rows > TILE_ROWS) tile_rows = TILE_ROWS;

        // ---- compute: thread-per-row (stride-85 LDS = conflict-free) ----
        float* ob = out_base + (it & 1) * OUT_FLOATS;
        if (tid < tile_rows) {
            const float* row = in_base + slot * TILE_FLOATS + tid * N_CH;

            const float x    = row[0];
            const float y    = row[1];
            const float w    = row[2];
            const float h    = row[3];
            const float conf = row[4];

            float b0 = row[5 +  0], b1 = row[5 + 20], b2 = row[5 + 40], b3 = row[5 + 60];
            int   i0 = 0,           i1 = 20,          i2 = 40,          i3 = 60;

            #pragma unroll
            for (int c = 1; c < 20; c++) {
                float v0 = row[5 +  0 + c];
                float v1 = row[5 + 20 + c];
                float v2 = row[5 + 40 + c];
                float v3 = row[5 + 60 + c];
                if (v0 > b0) { b0 = v0; i0 =  0 + c; }
                if (v1 > b1) { b1 = v1; i1 = 20 + c; }
                if (v2 > b2) { b2 = v2; i2 = 40 + c; }
                if (v3 > b3) { b3 = v3; i3 = 60 + c; }
            }
            // Ordered merge: ties keep the earlier quarter -> first-index semantics.
            if (b1 > b0) { b0 = b1; i0 = i1; }
            if (b2 > b0) { b0 = b2; i0 = i2; }
            if (b3 > b0) { b0 = b3; i0 = i3; }

            const float score = conf * b0;
            const bool  pass  = score > CONF_TH;
            const float hw = 0.5f * w;
            const float hh = 0.5f * h;

            float o0 = 0.f, o1 = 0.f, o2 = 0.f, o3 = 0.f, o4 = 0.f, o5 = 0.f;
            if (pass) {
                o0 = x - hw;
                o1 = y - hh;
                o2 = x + hw;
                o3 = y + hh;
                o4 = score;
                o5 = (float)i0;
            }

            float* so = ob + tid * N_OUT;
            so[0] = o0; so[1] = o1; so[2] = o2; so[3] = o3; so[4] = o4; so[5] = o5;
        }
        __syncthreads();   // LDS reads of in-buf done (slot reuse safe) + staging visible

        // ---- coalesced float4 store, evict-first via cache_hint ----
        {
            const int nvec = (tile_rows * N_OUT) / 4;   // <= 192 (tile_rows % 4 == 0)
            const float4* src = reinterpret_cast<const float4*>(ob);
            float4* dst = reinterpret_cast<float4*>(
                reinterpret_cast<float*>(out4) + (size_t)(row0 + r_off) * N_OUT);
            for (int i = tid; i < nvec; i += BLOCK_THREADS)
                stg128_ef(dst + i, src[i], pol);
        }
    }
}

extern "C" void kernel_launch(void* const* d_in, const int* in_sizes, int n_in,
                              void* d_out, int out_size)
{
    const float* in  = (const float*)d_in[0];
    float4*      out = (float4*)d_out;
    cudaFuncSetAttribute(yolo_post_kernel,
                         cudaFuncAttributeMaxDynamicSharedMemorySize, SM_TOTAL);
    yolo_post_kernel<<<GRID_BLOCKS, BLOCK_THREADS, SM_TOTAL>>>(in, out);
}